// round 3
// baseline (speedup 1.0000x reference)
#include <cuda_runtime.h>
#include <cstdint>

// Problem constants (fixed by the dataset)
#define ROWS        8192
#define COLS        8192
#define NUMEL       (ROWS * COLS)            // 67,108,864
#define CENTROID_LEN 4
#define NGROUPS     (NUMEL / CENTROID_LEN)   // 16,777,216 groups of 4 floats
#define HALF_GROUPS (NGROUPS / 2)            // 8,388,608 -> codebook boundary
#define NQUADS      (NGROUPS / 4)            // 4,194,304 quads (4 groups each)
#define CB_ROWS     512                      // 2 codebooks * 256 centroids

#define NCTA  4096
#define TPB   256
#define QPT   (NQUADS / (NCTA * TPB))        // 4 quads per thread, all in flight

__global__ __launch_bounds__(TPB, 5)         // cap regs at 51 -> 5 CTAs/SM
void dequant_kernel(const float4* __restrict__ codebooks,   // 512 x float4 (8KB)
                    const float*  __restrict__ scales,      // numel/64 floats
                    const int4*   __restrict__ codes,       // NQUADS int4
                    float4*       __restrict__ out)         // NGROUPS float4
{
    __shared__ float4 scb[CB_ROWS];

    int t = threadIdx.x;
    #pragma unroll
    for (int i = t; i < CB_ROWS; i += TPB)
        scb[i] = codebooks[i];
    __syncthreads();

    // Block owns quads [blockStart, blockStart + TPB*QPT) = 1024 quads.
    unsigned int blockStart = blockIdx.x * (TPB * QPT);

    // 1024-quad block range never straddles the codebook-half boundary
    // (HALF_GROUPS/4 = 2,097,152 is a multiple of 1024) -> uniform base.
    const float4* cb = scb + ((blockStart * 4u >= HALF_GROUPS) ? 256 : 0);

    unsigned int q0 = blockStart + t;

    // Issue ALL independent global loads up front (MLP = 4 codes + scales).
    int4  c[QPT];
    float s[QPT];
    #pragma unroll
    for (int j = 0; j < QPT; j++)
        c[j] = __ldcs(&codes[q0 + (unsigned)j * TPB]);   // read-once, evict-first
    #pragma unroll
    for (int j = 0; j < QPT; j++)
        s[j] = __ldg(&scales[(q0 + (unsigned)j * TPB) >> 2]);

    #pragma unroll
    for (int j = 0; j < QPT; j++) {
        float4 v0 = cb[c[j].x];
        float4 v1 = cb[c[j].y];
        float4 v2 = cb[c[j].z];
        float4 v3 = cb[c[j].w];
        float sj = s[j];
        v0.x *= sj; v0.y *= sj; v0.z *= sj; v0.w *= sj;
        v1.x *= sj; v1.y *= sj; v1.z *= sj; v1.w *= sj;
        v2.x *= sj; v2.y *= sj; v2.z *= sj; v2.w *= sj;
        v3.x *= sj; v3.y *= sj; v3.z *= sj; v3.w *= sj;

        float4* o = out + (size_t)(q0 + (unsigned)j * TPB) * 4u;
        __stcs(o + 0, v0);   // write-once, streaming
        __stcs(o + 1, v1);
        __stcs(o + 2, v2);
        __stcs(o + 3, v3);
    }
}

extern "C" void kernel_launch(void* const* d_in, const int* in_sizes, int n_in,
                              void* d_out, int out_size)
{
    const float4* codebooks = (const float4*)d_in[0];  // [2,256,4] fp32
    const float*  scales    = (const float*) d_in[1];  // [numel/64, 1] fp32
    const int4*   codes     = (const int4*)  d_in[2];  // [2, numel/8] int32
    float4*       out       = (float4*)d_out;          // [8192, 8192] fp32

    dequant_kernel<<<NCTA, TPB>>>(codebooks, scales, codes, out);
}

// round 4
// speedup vs baseline: 1.3098x; 1.3098x over previous
#include <cuda_runtime.h>
#include <cstdint>

#define NUMEL        (8192 * 8192)            // 67,108,864
#define NGROUPS      (NUMEL / 4)              // 16,777,216 float4 groups
#define HALF_GROUPS  (NGROUPS / 2)            // codebook boundary
#define CB_ROWS      512                      // 2 codebooks * 256 centroids

#define TPB          256
#define JITER        4                        // groups per thread per tile
#define TILE_GROUPS  (TPB * JITER)            // 1024 groups = 16KB
#define TILE_BYTES   (TILE_GROUPS * 16)       // 16384
#define NTILES       (NGROUPS / TILE_GROUPS)  // 16384
#define GRID         740                      // 148 SMs * 5 CTAs, persistent

__device__ __forceinline__ uint32_t smem_u32(const void* p) {
    uint32_t a;
    asm("{ .reg .u64 t; cvta.to.shared.u64 t, %1; cvt.u32.u64 %0, t; }"
        : "=r"(a) : "l"(p));
    return a;
}

__global__ __launch_bounds__(TPB, 5)
void dequant_kernel(const float4* __restrict__ codebooks,   // 512 x float4 (8KB)
                    const float*  __restrict__ scales,      // NGROUPS/4 floats
                    const int*    __restrict__ codes,       // NGROUPS ints
                    float4*       __restrict__ out)         // NGROUPS float4
{
    __shared__ float4 scb[CB_ROWS];                 // 8KB codebook
    __shared__ float4 obuf[2][TILE_GROUPS];         // 2 x 16KB output staging

    int t = threadIdx.x;
    #pragma unroll
    for (int i = t; i < CB_ROWS; i += TPB)
        scb[i] = codebooks[i];
    __syncthreads();

    unsigned int it = 0;
    for (unsigned int tile = blockIdx.x; tile < NTILES; tile += GRID, ++it) {
        int b = it & 1;

        // Reclaim buffer b: wait until the bulk store issued 2 tiles ago has
        // finished READING smem (wait_group.read), then release all threads.
        if (it >= 2 && t == 0)
            asm volatile("cp.async.bulk.wait_group.read 1;" ::: "memory");
        __syncthreads();

        unsigned int gbase = tile * TILE_GROUPS;
        // 1024-group tile never straddles the codebook-half boundary.
        const float4* cb = scb + ((gbase >= HALF_GROUPS) ? 256 : 0);

        // All independent global loads first (MLP = 8).
        int   c[JITER];
        float s[JITER];
        #pragma unroll
        for (int j = 0; j < JITER; j++)
            c[j] = __ldcs(&codes[gbase + (unsigned)j * TPB + t]);
        #pragma unroll
        for (int j = 0; j < JITER; j++)
            s[j] = __ldg(&scales[(gbase + (unsigned)j * TPB + t) >> 4]);

        // Gather + scale + conflict-free STS (linear 16B per lane).
        #pragma unroll
        for (int j = 0; j < JITER; j++) {
            float4 v = cb[c[j]];
            float sj = s[j];
            v.x *= sj; v.y *= sj; v.z *= sj; v.w *= sj;
            obuf[b][j * TPB + t] = v;
        }
        __syncthreads();

        // One thread hands the 16KB tile to the TMA engine.
        if (t == 0) {
            asm volatile("fence.proxy.async.shared::cta;" ::: "memory");
            uint32_t saddr = smem_u32(&obuf[b][0]);
            const float4* gdst = out + gbase;
            asm volatile(
                "cp.async.bulk.global.shared::cta.bulk_group [%0], [%1], %2;"
                :: "l"(gdst), "r"(saddr), "r"((int)TILE_BYTES) : "memory");
            asm volatile("cp.async.bulk.commit_group;" ::: "memory");
        }
    }

    // Drain all outstanding bulk stores before exit.
    if (t == 0)
        asm volatile("cp.async.bulk.wait_group 0;" ::: "memory");
}

extern "C" void kernel_launch(void* const* d_in, const int* in_sizes, int n_in,
                              void* d_out, int out_size)
{
    const float4* codebooks = (const float4*)d_in[0];  // [2,256,4] fp32
    const float*  scales    = (const float*) d_in[1];  // [numel/64, 1] fp32
    const int*    codes     = (const int*)   d_in[2];  // [2, numel/8] int32 flat
    float4*       out       = (float4*)d_out;          // [8192, 8192] fp32

    dequant_kernel<<<GRID, TPB>>>(codebooks, scales, codes, out);
}

// round 5
// speedup vs baseline: 1.3475x; 1.0288x over previous
#include <cuda_runtime.h>
#include <cstdint>

#define NUMEL        (8192 * 8192)            // 67,108,864
#define NGROUPS      (NUMEL / 4)              // 16,777,216 float4 groups
#define HALF_GROUPS  (NGROUPS / 2)            // codebook boundary
#define CB_ROWS      512                      // 2 codebooks * 256 centroids

#define TPB          512
#define JITER        2                        // groups per thread per tile
#define TILE_GROUPS  (TPB * JITER)            // 1024 groups = 16KB
#define TILE_BYTES   (TILE_GROUPS * 16)       // 16384
#define NTILES       (NGROUPS / TILE_GROUPS)  // 16384
#define GRID         (148 * 4)                // 592 persistent CTAs, 4/SM

__device__ __forceinline__ uint32_t smem_u32(const void* p) {
    uint32_t a;
    asm("{ .reg .u64 t; cvta.to.shared.u64 t, %1; cvt.u32.u64 %0, t; }"
        : "=r"(a) : "l"(p));
    return a;
}

__global__ __launch_bounds__(TPB, 4)          // 2048 thr/SM -> <=32 regs
void dequant_kernel(const float4* __restrict__ codebooks,   // 512 x float4 (8KB)
                    const float*  __restrict__ scales,      // NGROUPS/4 floats
                    const int*    __restrict__ codes,       // NGROUPS ints
                    float4*       __restrict__ out)         // NGROUPS float4
{
    __shared__ float4 scb[CB_ROWS];                 // 8KB codebook
    __shared__ float4 obuf[2][TILE_GROUPS];         // 2 x 16KB staging

    int t = threadIdx.x;
    // 512 threads -> one codebook row each
    scb[t] = codebooks[t];
    __syncthreads();

    // ---- prologue: prefetch first tile's codes + scales ----
    unsigned int tile = blockIdx.x;
    int   c[JITER];
    float s[JITER];
    {
        unsigned int gbase = tile * TILE_GROUPS;
        #pragma unroll
        for (int j = 0; j < JITER; j++)
            c[j] = __ldcs(&codes[gbase + (unsigned)j * TPB + t]);
        #pragma unroll
        for (int j = 0; j < JITER; j++)
            s[j] = __ldg(&scales[(gbase + (unsigned)j * TPB + t) >> 4]);
    }

    unsigned int it = 0;
    for (; tile < NTILES; tile += GRID, ++it) {
        int b = it & 1;
        unsigned int gbase = tile * TILE_GROUPS;
        // 1024-group tile never straddles the codebook-half boundary.
        const float4* cb = scb + ((gbase >= HALF_GROUPS) ? 256 : 0);

        // Gather + scale into registers (consumes c/s for THIS tile).
        float4 v[JITER];
        #pragma unroll
        for (int j = 0; j < JITER; j++) {
            float4 g = cb[c[j]];
            float sj = s[j];
            g.x *= sj; g.y *= sj; g.z *= sj; g.w *= sj;
            v[j] = g;
        }

        // Prefetch NEXT tile's codes/scales — overlaps barriers + TMA below.
        unsigned int ntile = tile + GRID;
        if (ntile < NTILES) {
            unsigned int nbase = ntile * TILE_GROUPS;
            #pragma unroll
            for (int j = 0; j < JITER; j++)
                c[j] = __ldcs(&codes[nbase + (unsigned)j * TPB + t]);
            #pragma unroll
            for (int j = 0; j < JITER; j++)
                s[j] = __ldg(&scales[(nbase + (unsigned)j * TPB + t) >> 4]);
        }

        // Reclaim buffer b: the bulk store issued 2 tiles ago must have
        // finished READING smem.
        if (it >= 2 && t == 0)
            asm volatile("cp.async.bulk.wait_group.read 1;" ::: "memory");
        __syncthreads();

        // Conflict-free STS.128 (linear 16B per lane).
        #pragma unroll
        for (int j = 0; j < JITER; j++)
            obuf[b][j * TPB + t] = v[j];
        __syncthreads();

        // Hand the 16KB tile to the TMA engine.
        if (t == 0) {
            asm volatile("fence.proxy.async.shared::cta;" ::: "memory");
            uint32_t saddr = smem_u32(&obuf[b][0]);
            const float4* gdst = out + gbase;
            asm volatile(
                "cp.async.bulk.global.shared::cta.bulk_group [%0], [%1], %2;"
                :: "l"(gdst), "r"(saddr), "r"((int)TILE_BYTES) : "memory");
            asm volatile("cp.async.bulk.commit_group;" ::: "memory");
        }
    }

    // Drain all outstanding bulk stores before exit.
    if (t == 0)
        asm volatile("cp.async.bulk.wait_group 0;" ::: "memory");
}

extern "C" void kernel_launch(void* const* d_in, const int* in_sizes, int n_in,
                              void* d_out, int out_size)
{
    const float4* codebooks = (const float4*)d_in[0];  // [2,256,4] fp32
    const float*  scales    = (const float*) d_in[1];  // [numel/64, 1] fp32
    const int*    codes     = (const int*)   d_in[2];  // [2, numel/8] int32 flat
    float4*       out       = (float4*)d_out;          // [8192, 8192] fp32

    dequant_kernel<<<GRID, TPB>>>(codebooks, scales, codes, out);
}